// round 1
// baseline (speedup 1.0000x reference)
#include <cuda_runtime.h>
#include <cuda_bf16.h>
#include <math_constants.h>

// ---------------- problem constants ----------------
#define BB   16
#define TT   2048
#define INC  80
#define HC   512
#define DC   512
#define KC   1024
#define RR   (BB*TT)          // 32768 rows (b,t)

// ---------------- scratch (device globals; no allocations allowed) -------
__device__ float g_bufA[(size_t)RR * DC];     // 64 MB
__device__ float g_bufB[(size_t)RR * DC];     // 64 MB
__device__ float g_wt[3*DC*DC + 3*INC*HC + 3*DC*HC + 3*HC*INC]; // transformed weights, regions
__device__ float g_cbT[DC * KC];              // codebook transposed [D, K]
__device__ float g_cnorm[KC];
__device__ int   g_idx[RR];

// offsets into g_wt (floats)
#define WT_OFF_E1 0                         // [240, 512]
#define WT_OFF_E2 (WT_OFF_E1 + 3*INC*HC)    // [1536, 512]
#define WT_OFF_D1 (WT_OFF_E2 + 3*HC*DC)     // [1536, 512]
#define WT_OFF_D2 (WT_OFF_D1 + 3*DC*HC)     // [1536, 80]

// ---------------- weight transform: w[Cout,Cin,3] -> wt[3*Cin, Cout] ------
__global__ void k_wtransform(const float* __restrict__ w, float* __restrict__ wt,
                             int Cin, int Cout) {
    int n = 3 * Cin * Cout;
    for (int i = blockIdx.x * blockDim.x + threadIdx.x; i < n;
         i += gridDim.x * blockDim.x) {
        int k  = i / Cout;
        int co = i - k * Cout;
        int dt = k / Cin;
        int ci = k - dt * Cin;
        wt[i] = w[(co * Cin + ci) * 3 + dt];
    }
}

// ---------------- codebook transpose + norms -----------------------------
__global__ void k_cbT(const float* __restrict__ cb) {
    int n = DC * KC;
    for (int i = blockIdx.x * blockDim.x + threadIdx.x; i < n;
         i += gridDim.x * blockDim.x) {
        int d = i >> 10;            // / KC
        int k = i & (KC - 1);
        g_cbT[i] = cb[k * DC + d];
    }
}

__global__ void k_cnorm(const float* __restrict__ cb) {
    int k = blockIdx.x;
    float s = 0.f;
    for (int d = threadIdx.x; d < DC; d += 256) {
        float v = cb[k * DC + d];
        s += v * v;
    }
    __shared__ float red[256];
    red[threadIdx.x] = s;
    __syncthreads();
    for (int o = 128; o > 0; o >>= 1) {
        if (threadIdx.x < o) red[threadIdx.x] += red[threadIdx.x + o];
        __syncthreads();
    }
    if (threadIdx.x == 0) g_cnorm[k] = red[0];
}

// ---------------- implicit-im2col conv GEMM ------------------------------
// in:  [R, Cin] channel-last.  wt: [3*Cin, Cout].  out: [R, Cout]
// A[r, k] = in[r*Cin + k - Cin], zero when (dt==0 && t==0) || (dt==2 && t==T-1)
__global__ __launch_bounds__(256)
void k_convgemm(const float* __restrict__ A, const float* __restrict__ W,
                const float* __restrict__ bias, float* __restrict__ C,
                int Cin, int Cout, int relu) {
    const int BM = 128, BN = 128, BK = 16;
    __shared__ float As[BK][BM];
    __shared__ float Bs[BK][BN];

    int tid = threadIdx.x;
    int tx = tid & 15, ty = tid >> 4;
    int rowBase = blockIdx.y * BM;
    int colBase = blockIdx.x * BN;
    int Keff = 3 * Cin;

    // precompute per-rep row info for A loads (2 float4 per thread)
    int ar0 = (tid) >> 2;            int ak0 = (tid & 3) << 2;
    int ar1 = (tid + 256) >> 2;      int ak1 = ((tid + 256) & 3) << 2;
    int r0 = rowBase + ar0, r1 = rowBase + ar1;
    int t0 = r0 & (TT - 1), t1 = r1 & (TT - 1);
    const float* arow0 = A + (size_t)r0 * Cin - Cin;
    const float* arow1 = A + (size_t)r1 * Cin - Cin;
    bool f0 = (t0 == 0), l0 = (t0 == TT - 1);
    bool f1 = (t1 == 0), l1 = (t1 == TT - 1);

    float acc[8][8];
#pragma unroll
    for (int i = 0; i < 8; i++)
#pragma unroll
        for (int j = 0; j < 8; j++) acc[i][j] = 0.f;

    for (int k0 = 0; k0 < Keff; k0 += BK) {
        int dt = k0 / Cin;  // whole chunk in one dt (Cin multiple of 16)
        float4 v;
        bool z0 = (dt == 0 && f0) || (dt == 2 && l0);
        v = z0 ? make_float4(0.f, 0.f, 0.f, 0.f)
               : *(const float4*)(arow0 + k0 + ak0);
        As[ak0 + 0][ar0] = v.x; As[ak0 + 1][ar0] = v.y;
        As[ak0 + 2][ar0] = v.z; As[ak0 + 3][ar0] = v.w;
        bool z1 = (dt == 0 && f1) || (dt == 2 && l1);
        v = z1 ? make_float4(0.f, 0.f, 0.f, 0.f)
               : *(const float4*)(arow1 + k0 + ak1);
        As[ak1 + 0][ar1] = v.x; As[ak1 + 1][ar1] = v.y;
        As[ak1 + 2][ar1] = v.z; As[ak1 + 3][ar1] = v.w;

#pragma unroll
        for (int rep = 0; rep < 2; rep++) {
            int idx4 = tid + rep * 256;
            int br = idx4 >> 5;
            int bc = (idx4 & 31) << 2;
            int co = colBase + bc;
            float4 bv = make_float4(0.f, 0.f, 0.f, 0.f);
            if (co < Cout)
                bv = *(const float4*)(W + (size_t)(k0 + br) * Cout + co);
            *(float4*)&Bs[br][bc] = bv;
        }
        __syncthreads();

#pragma unroll
        for (int k = 0; k < BK; k++) {
            float a[8], b[8];
            *(float4*)(a)     = *(const float4*)&As[k][ty * 8];
            *(float4*)(a + 4) = *(const float4*)&As[k][ty * 8 + 4];
            *(float4*)(b)     = *(const float4*)&Bs[k][tx * 8];
            *(float4*)(b + 4) = *(const float4*)&Bs[k][tx * 8 + 4];
#pragma unroll
            for (int i = 0; i < 8; i++)
#pragma unroll
                for (int j = 0; j < 8; j++)
                    acc[i][j] = fmaf(a[i], b[j], acc[i][j]);
        }
        __syncthreads();
    }

    // epilogue
#pragma unroll
    for (int i = 0; i < 8; i++) {
        int r = rowBase + ty * 8 + i;
#pragma unroll
        for (int j4 = 0; j4 < 8; j4 += 4) {
            int co = colBase + tx * 8 + j4;
            if (co < Cout) {
                float4 v;
                v.x = acc[i][j4 + 0] + bias[co + 0];
                v.y = acc[i][j4 + 1] + bias[co + 1];
                v.z = acc[i][j4 + 2] + bias[co + 2];
                v.w = acc[i][j4 + 3] + bias[co + 3];
                if (relu) {
                    v.x = fmaxf(v.x, 0.f); v.y = fmaxf(v.y, 0.f);
                    v.z = fmaxf(v.z, 0.f); v.w = fmaxf(v.w, 0.f);
                }
                *(float4*)(C + (size_t)r * Cout + co) = v;
            }
        }
    }
}

// ---------------- VQ: fused scores GEMM + argmin -------------------------
// Z: [R, D].  CBT: [D, K].  score = cnorm[k] - 2*dot(z, c_k); argmin over k.
__global__ __launch_bounds__(256)
void k_vq(const float* __restrict__ Z, float* __restrict__ idxOutF) {
    const int BM = 128, BK = 16, BN = 128;
    __shared__ float As[BK][BM];
    __shared__ float Bs[BK][BN];
    __shared__ float sval[128][17];
    __shared__ int   sidx[128][17];

    int tid = threadIdx.x;
    int tx = tid & 15, ty = tid >> 4;
    int rowBase = blockIdx.x * BM;

    int ar0 = tid >> 2;          int ak0 = (tid & 3) << 2;
    int ar1 = (tid + 256) >> 2;  int ak1 = ((tid + 256) & 3) << 2;
    const float* arow0 = Z + (size_t)(rowBase + ar0) * DC;
    const float* arow1 = Z + (size_t)(rowBase + ar1) * DC;

    float minv[8];
    int   mini[8];
#pragma unroll
    for (int i = 0; i < 8; i++) { minv[i] = CUDART_INF_F; mini[i] = 0; }

    for (int nb = 0; nb < KC; nb += BN) {
        float acc[8][8];
#pragma unroll
        for (int i = 0; i < 8; i++)
#pragma unroll
            for (int j = 0; j < 8; j++) acc[i][j] = 0.f;

        for (int d0 = 0; d0 < DC; d0 += BK) {
            float4 v;
            v = *(const float4*)(arow0 + d0 + ak0);
            As[ak0 + 0][ar0] = v.x; As[ak0 + 1][ar0] = v.y;
            As[ak0 + 2][ar0] = v.z; As[ak0 + 3][ar0] = v.w;
            v = *(const float4*)(arow1 + d0 + ak1);
            As[ak1 + 0][ar1] = v.x; As[ak1 + 1][ar1] = v.y;
            As[ak1 + 2][ar1] = v.z; As[ak1 + 3][ar1] = v.w;
#pragma unroll
            for (int rep = 0; rep < 2; rep++) {
                int idx4 = tid + rep * 256;
                int br = idx4 >> 5;
                int bc = (idx4 & 31) << 2;
                *(float4*)&Bs[br][bc] =
                    *(const float4*)(g_cbT + (size_t)(d0 + br) * KC + nb + bc);
            }
            __syncthreads();
#pragma unroll
            for (int k = 0; k < BK; k++) {
                float a[8], b[8];
                *(float4*)(a)     = *(const float4*)&As[k][ty * 8];
                *(float4*)(a + 4) = *(const float4*)&As[k][ty * 8 + 4];
                *(float4*)(b)     = *(const float4*)&Bs[k][tx * 8];
                *(float4*)(b + 4) = *(const float4*)&Bs[k][tx * 8 + 4];
#pragma unroll
                for (int i = 0; i < 8; i++)
#pragma unroll
                    for (int j = 0; j < 8; j++)
                        acc[i][j] = fmaf(a[i], b[j], acc[i][j]);
            }
            __syncthreads();
        }

        // running argmin update (ascending k -> first-min wins on strict <)
#pragma unroll
        for (int j = 0; j < 8; j++) {
            int kk = nb + tx * 8 + j;
            float cn = g_cnorm[kk];
#pragma unroll
            for (int i = 0; i < 8; i++) {
                float s = fmaf(-2.f, acc[i][j], cn);
                if (s < minv[i]) { minv[i] = s; mini[i] = kk; }
            }
        }
    }

#pragma unroll
    for (int i = 0; i < 8; i++) {
        sval[ty * 8 + i][tx] = minv[i];
        sidx[ty * 8 + i][tx] = mini[i];
    }
    __syncthreads();
    if (tid < 128) {
        float bv = sval[tid][0];
        int   bi = sidx[tid][0];
#pragma unroll
        for (int x = 1; x < 16; x++) {
            float v = sval[tid][x];
            int   ii = sidx[tid][x];
            if (v < bv || (v == bv && ii < bi)) { bv = v; bi = ii; }
        }
        g_idx[rowBase + tid] = bi;
        if (idxOutF) idxOutF[rowBase + tid] = (float)bi;
    }
}

// ---------------- gather quantized vectors -------------------------------
__global__ void k_gather(const float* __restrict__ cb, float* __restrict__ q) {
    int n = RR * (DC / 4);
    for (int i = blockIdx.x * blockDim.x + threadIdx.x; i < n;
         i += gridDim.x * blockDim.x) {
        int r = i >> 7;             // / (DC/4)
        int c = i & 127;
        ((float4*)q)[i] =
            ((const float4*)cb)[(size_t)g_idx[r] * (DC / 4) + c];
    }
}

// ---------------- launch ---------------------------------------------------
extern "C" void kernel_launch(void* const* d_in, const int* in_sizes, int n_in,
                              void* d_out, int out_size) {
    const float* mels   = (const float*)d_in[0];
    const float* enc_w1 = (const float*)d_in[1];
    const float* enc_b1 = (const float*)d_in[2];
    const float* enc_w2 = (const float*)d_in[3];
    const float* enc_b2 = (const float*)d_in[4];
    const float* cb     = (const float*)d_in[5];
    const float* dec_w1 = (const float*)d_in[6];
    const float* dec_b1 = (const float*)d_in[7];
    const float* dec_w2 = (const float*)d_in[8];
    const float* dec_b2 = (const float*)d_in[9];

    float *bufA, *bufB, *wt;
    cudaGetSymbolAddress((void**)&bufA, g_bufA);
    cudaGetSymbolAddress((void**)&bufB, g_bufB);
    cudaGetSymbolAddress((void**)&wt,   g_wt);

    float* out = (float*)d_out;
    float* idxOutF = (out_size >= RR * INC + RR) ? (out + (size_t)RR * INC) : nullptr;

    // prep: transform all weights + codebook transpose + norms
    k_wtransform<<<256, 256>>>(enc_w1, wt + WT_OFF_E1, INC, HC);
    k_wtransform<<<512, 256>>>(enc_w2, wt + WT_OFF_E2, HC, DC);
    k_wtransform<<<512, 256>>>(dec_w1, wt + WT_OFF_D1, DC, HC);
    k_wtransform<<<256, 256>>>(dec_w2, wt + WT_OFF_D2, HC, INC);
    k_cbT<<<512, 256>>>(cb);
    k_cnorm<<<KC, 256>>>(cb);

    dim3 g512(HC / 128, RR / 128);   // (4, 256)
    dim3 g80(1, RR / 128);           // Cout=80 -> one col tile

    // encoder
    k_convgemm<<<g512, 256>>>(mels, wt + WT_OFF_E1, enc_b1, bufA, INC, HC, 1);
    k_convgemm<<<g512, 256>>>(bufA, wt + WT_OFF_E2, enc_b2, bufB, HC, DC, 0);

    // VQ (z in bufB)
    k_vq<<<RR / 128, 256>>>(bufB, idxOutF);

    // gather quantized into bufA
    k_gather<<<1024, 256>>>(cb, bufA);

    // decoder
    k_convgemm<<<g512, 256>>>(bufA, wt + WT_OFF_D1, dec_b1, bufB, DC, HC, 1);
    k_convgemm<<<g80,  256>>>(bufB, wt + WT_OFF_D2, dec_b2, out, HC, INC, 0);
}

// round 3
// speedup vs baseline: 1.1851x; 1.1851x over previous
#include <cuda_runtime.h>
#include <cuda_bf16.h>
#include <math_constants.h>

// ---------------- problem constants ----------------
#define BB   16
#define TT   2048
#define INC  80
#define HC   512
#define DC   512
#define KC   1024
#define RR   (BB*TT)          // 32768 rows (b,t)

// ---------------- scratch (device globals; no allocations allowed) -------
__device__ float g_bufA[(size_t)RR * DC];     // 64 MB
__device__ float g_bufB[(size_t)RR * DC];     // 64 MB
__device__ float g_wt[3*INC*HC + 3*HC*DC + 3*DC*HC + 3*HC*INC];
__device__ float g_cbT[DC * KC];              // codebook transposed [D, K]
__device__ float g_cnorm[KC];
__device__ int   g_idx[RR];

// offsets into g_wt (floats)
#define WT_OFF_E1 0                         // [240, 512]
#define WT_OFF_E2 (WT_OFF_E1 + 3*INC*HC)    // [1536, 512]
#define WT_OFF_D1 (WT_OFF_E2 + 3*HC*DC)     // [1536, 512]
#define WT_OFF_D2 (WT_OFF_D1 + 3*DC*HC)     // [1536, 80]

// ---------------- weight transform: w[Cout,Cin,3] -> wt[3*Cin, Cout] ------
__global__ void k_wtransform(const float* __restrict__ w, float* __restrict__ wt,
                             int Cin, int Cout) {
    int n = 3 * Cin * Cout;
    for (int i = blockIdx.x * blockDim.x + threadIdx.x; i < n;
         i += gridDim.x * blockDim.x) {
        int k  = i / Cout;
        int co = i - k * Cout;
        int dt = k / Cin;
        int ci = k - dt * Cin;
        wt[i] = w[(co * Cin + ci) * 3 + dt];
    }
}

// ---------------- codebook transpose + norms -----------------------------
__global__ void k_cbT(const float* __restrict__ cb) {
    int n = DC * KC;
    for (int i = blockIdx.x * blockDim.x + threadIdx.x; i < n;
         i += gridDim.x * blockDim.x) {
        int d = i >> 10;            // / KC
        int k = i & (KC - 1);
        g_cbT[i] = cb[k * DC + d];
    }
}

__global__ void k_cnorm(const float* __restrict__ cb) {
    int k = blockIdx.x;
    float s = 0.f;
    for (int d = threadIdx.x; d < DC; d += 256) {
        float v = cb[k * DC + d];
        s += v * v;
    }
    __shared__ float red[256];
    red[threadIdx.x] = s;
    __syncthreads();
    for (int o = 128; o > 0; o >>= 1) {
        if (threadIdx.x < o) red[threadIdx.x] += red[threadIdx.x + o];
        __syncthreads();
    }
    if (threadIdx.x == 0) g_cnorm[k] = red[0];
}

// ---------------- implicit-im2col conv GEMM, double-buffered --------------
// Normal mode:  A is [R, CIN] channel-last activations.
// GATHER mode:  A is the codebook [K, CIN]; row r of the logical input is
//               codebook[g_idx[r]] (fuses the VQ gather into the conv).
// W: [3*CIN, COUT].  C: [R, COUT].
template<int CIN, int COUT, bool RELU, bool GATHER>
__global__ __launch_bounds__(256)
void k_convgemm(const float* __restrict__ A, const float* __restrict__ W,
                const float* __restrict__ bias, float* __restrict__ C) {
    constexpr int BM = 128, BN = 128, BK = 16, KEFF = 3 * CIN;
    __shared__ float As[2][BK][BM];
    __shared__ float Bs[2][BK][BN];

    const int tid = threadIdx.x;
    const int tx = tid & 15, ty = tid >> 4;
    const int rowBase = blockIdx.y * BM;
    const int colBase = blockIdx.x * BN;

    // A-load geometry: 2 float4 per thread (rows ar0, ar0+64; k-phase ak0)
    const int ar0 = tid >> 2, ak0 = (tid & 3) << 2;
    const int ar1 = ar0 + 64;
    const int r0 = rowBase + ar0, r1 = rowBase + ar1;
    const int t0 = r0 & (TT - 1), t1 = r1 & (TT - 1);
    const bool f0 = (t0 == 0), l0 = (t0 == TT - 1);
    const bool f1 = (t1 == 0), l1 = (t1 == TT - 1);

    // B-load geometry: 2 float4 per thread (rows br0, br0+8)
    const int br0 = tid >> 5;
    const int bc0 = (tid & 31) << 2;
    const int co0 = colBase + bc0;

    int gi0[3], gi1[3];
    if (GATHER) {
#pragma unroll
        for (int dt = 0; dt < 3; dt++) {
            int rr0 = r0 + dt - 1; rr0 = rr0 < 0 ? 0 : (rr0 >= RR ? RR - 1 : rr0);
            int rr1 = r1 + dt - 1; rr1 = rr1 < 0 ? 0 : (rr1 >= RR ? RR - 1 : rr1);
            gi0[dt] = g_idx[rr0];
            gi1[dt] = g_idx[rr1];
        }
    }

    float4 ra0, ra1, rb0, rb1;

    auto fetch = [&](int k0) {
        const int dt = k0 / CIN;                  // whole BK chunk in one tap
        const int ci = k0 - dt * CIN + ak0;
        const bool z0 = (dt == 0 && f0) || (dt == 2 && l0);
        const bool z1 = (dt == 0 && f1) || (dt == 2 && l1);
        const float *p0, *p1;
        if (GATHER) {
            p0 = A + (size_t)gi0[dt] * CIN + ci;
            p1 = A + (size_t)gi1[dt] * CIN + ci;
        } else {
            p0 = A + (size_t)(r0 + dt - 1) * CIN + ci;
            p1 = A + (size_t)(r1 + dt - 1) * CIN + ci;
        }
        ra0 = z0 ? make_float4(0.f, 0.f, 0.f, 0.f) : *(const float4*)p0;
        ra1 = z1 ? make_float4(0.f, 0.f, 0.f, 0.f) : *(const float4*)p1;
        if ((COUT % BN) != 0 && co0 >= COUT) {
            rb0 = make_float4(0.f, 0.f, 0.f, 0.f);
            rb1 = rb0;
        } else {
            rb0 = *(const float4*)(W + (size_t)(k0 + br0) * COUT + co0);
            rb1 = *(const float4*)(W + (size_t)(k0 + br0 + 8) * COUT + co0);
        }
    };

    auto stage = [&](int buf) {
        As[buf][ak0 + 0][ar0] = ra0.x; As[buf][ak0 + 1][ar0] = ra0.y;
        As[buf][ak0 + 2][ar0] = ra0.z; As[buf][ak0 + 3][ar0] = ra0.w;
        As[buf][ak0 + 0][ar1] = ra1.x; As[buf][ak0 + 1][ar1] = ra1.y;
        As[buf][ak0 + 2][ar1] = ra1.z; As[buf][ak0 + 3][ar1] = ra1.w;
        *(float4*)&Bs[buf][br0][bc0]     = rb0;
        *(float4*)&Bs[buf][br0 + 8][bc0] = rb1;
    };

    float acc[8][8] = {};

    auto compute = [&](int buf) {
#pragma unroll
        for (int k = 0; k < BK; k++) {
            float a[8], b[8];
            *(float4*)(a)     = *(const float4*)&As[buf][k][ty * 8];
            *(float4*)(a + 4) = *(const float4*)&As[buf][k][ty * 8 + 4];
            *(float4*)(b)     = *(const float4*)&Bs[buf][k][tx * 8];
            *(float4*)(b + 4) = *(const float4*)&Bs[buf][k][tx * 8 + 4];
#pragma unroll
            for (int i = 0; i < 8; i++)
#pragma unroll
                for (int j = 0; j < 8; j++)
                    acc[i][j] = fmaf(a[i], b[j], acc[i][j]);
        }
    };

    fetch(0);
    stage(0);
    __syncthreads();
    int buf = 0;
    for (int k0 = BK; k0 < KEFF; k0 += BK) {
        fetch(k0);            // prefetch next tile into regs
        compute(buf);         // compute current tile (hides load latency)
        stage(buf ^ 1);       // write prefetched tile into alternate buffer
        __syncthreads();
        buf ^= 1;
    }
    compute(buf);

    // epilogue
#pragma unroll
    for (int i = 0; i < 8; i++) {
        const int r = rowBase + ty * 8 + i;
#pragma unroll
        for (int j4 = 0; j4 < 8; j4 += 4) {
            const int co = colBase + tx * 8 + j4;
            if ((COUT % BN) == 0 || co < COUT) {
                float4 v;
                v.x = acc[i][j4 + 0] + bias[co + 0];
                v.y = acc[i][j4 + 1] + bias[co + 1];
                v.z = acc[i][j4 + 2] + bias[co + 2];
                v.w = acc[i][j4 + 3] + bias[co + 3];
                if (RELU) {
                    v.x = fmaxf(v.x, 0.f); v.y = fmaxf(v.y, 0.f);
                    v.z = fmaxf(v.z, 0.f); v.w = fmaxf(v.w, 0.f);
                }
                *(float4*)(C + (size_t)r * COUT + co) = v;
            }
        }
    }
}

// ---------------- VQ: fused scores GEMM + argmin, double-buffered ---------
// Z: [R, D].  g_cbT: [D, K].  score = cnorm[k] - 2*dot(z, c_k); argmin over k.
__global__ __launch_bounds__(256)
void k_vq(const float* __restrict__ Z, float* __restrict__ idxOutF) {
    constexpr int BM = 128, BN = 128, BK = 16;
    constexpr int KTILES = DC / BK;                 // 32
    constexpr int NITER = (KC / BN) * KTILES;       // 256
    __shared__ float As[2][BK][BM];
    __shared__ float Bs[2][BK][BN];
    __shared__ float sval[128][17];
    __shared__ int   sidx[128][17];

    const int tid = threadIdx.x;
    const int tx = tid & 15, ty = tid >> 4;
    const int rowBase = blockIdx.x * BM;
    const int ar0 = tid >> 2, ak0 = (tid & 3) << 2;
    const int ar1 = ar0 + 64;
    const int br0 = tid >> 5;
    const int bc0 = (tid & 31) << 2;
    const float* arow0 = Z + (size_t)(rowBase + ar0) * DC + ak0;
    const float* arow1 = Z + (size_t)(rowBase + ar1) * DC + ak0;

    float4 ra0, ra1, rb0, rb1;

    auto fetch = [&](int iter) {
        const int nb = (iter >> 5) << 7;    // N-tile base (iter/32 * 128)
        const int d0 = (iter & 31) << 4;    // K-tile base (iter%32 * 16)
        ra0 = *(const float4*)(arow0 + d0);
        ra1 = *(const float4*)(arow1 + d0);
        rb0 = *(const float4*)(g_cbT + (size_t)(d0 + br0) * KC + nb + bc0);
        rb1 = *(const float4*)(g_cbT + (size_t)(d0 + br0 + 8) * KC + nb + bc0);
    };

    auto stage = [&](int buf) {
        As[buf][ak0 + 0][ar0] = ra0.x; As[buf][ak0 + 1][ar0] = ra0.y;
        As[buf][ak0 + 2][ar0] = ra0.z; As[buf][ak0 + 3][ar0] = ra0.w;
        As[buf][ak0 + 0][ar1] = ra1.x; As[buf][ak0 + 1][ar1] = ra1.y;
        As[buf][ak0 + 2][ar1] = ra1.z; As[buf][ak0 + 3][ar1] = ra1.w;
        *(float4*)&Bs[buf][br0][bc0]     = rb0;
        *(float4*)&Bs[buf][br0 + 8][bc0] = rb1;
    };

    float acc[8][8];
    float minv[8];
    int   mini[8];
#pragma unroll
    for (int i = 0; i < 8; i++) { minv[i] = CUDART_INF_F; mini[i] = 0; }

    auto compute = [&](int buf) {
#pragma unroll
        for (int k = 0; k < BK; k++) {
            float a[8], b[8];
            *(float4*)(a)     = *(const float4*)&As[buf][k][ty * 8];
            *(float4*)(a + 4) = *(const float4*)&As[buf][k][ty * 8 + 4];
            *(float4*)(b)     = *(const float4*)&Bs[buf][k][tx * 8];
            *(float4*)(b + 4) = *(const float4*)&Bs[buf][k][tx * 8 + 4];
#pragma unroll
            for (int i = 0; i < 8; i++)
#pragma unroll
                for (int j = 0; j < 8; j++)
                    acc[i][j] = fmaf(a[i], b[j], acc[i][j]);
        }
    };

    fetch(0);
    stage(0);
    __syncthreads();
    int buf = 0;
    for (int iter = 0; iter < NITER; iter++) {
        if ((iter & (KTILES - 1)) == 0) {
#pragma unroll
            for (int i = 0; i < 8; i++)
#pragma unroll
                for (int j = 0; j < 8; j++) acc[i][j] = 0.f;
        }
        const bool more = (iter + 1 < NITER);
        if (more) fetch(iter + 1);
        compute(buf);
        if ((iter & (KTILES - 1)) == KTILES - 1) {
            // running argmin update (ascending k -> first-min wins on strict <)
            const int nb = (iter >> 5) << 7;
#pragma unroll
            for (int j = 0; j < 8; j++) {
                const int kk = nb + tx * 8 + j;
                const float cn = g_cnorm[kk];
#pragma unroll
                for (int i = 0; i < 8; i++) {
                    float s = fmaf(-2.f, acc[i][j], cn);
                    if (s < minv[i]) { minv[i] = s; mini[i] = kk; }
                }
            }
        }
        if (more) {
            stage(buf ^ 1);
            __syncthreads();
            buf ^= 1;
        }
    }

#pragma unroll
    for (int i = 0; i < 8; i++) {
        sval[ty * 8 + i][tx] = minv[i];
        sidx[ty * 8 + i][tx] = mini[i];
    }
    __syncthreads();
    if (tid < 128) {
        float bv = sval[tid][0];
        int   bi = sidx[tid][0];
#pragma unroll
        for (int x = 1; x < 16; x++) {
            float v = sval[tid][x];
            int   ii = sidx[tid][x];
            if (v < bv || (v == bv && ii < bi)) { bv = v; bi = ii; }
        }
        g_idx[rowBase + tid] = bi;
        if (idxOutF) idxOutF[rowBase + tid] = (float)bi;
    }
}

// ---------------- launch ---------------------------------------------------
extern "C" void kernel_launch(void* const* d_in, const int* in_sizes, int n_in,
                              void* d_out, int out_size) {
    const float* mels   = (const float*)d_in[0];
    const float* enc_w1 = (const float*)d_in[1];
    const float* enc_b1 = (const float*)d_in[2];
    const float* enc_w2 = (const float*)d_in[3];
    const float* enc_b2 = (const float*)d_in[4];
    const float* cb     = (const float*)d_in[5];
    const float* dec_w1 = (const float*)d_in[6];
    const float* dec_b1 = (const float*)d_in[7];
    const float* dec_w2 = (const float*)d_in[8];
    const float* dec_b2 = (const float*)d_in[9];

    float *bufA, *bufB, *wt;
    cudaGetSymbolAddress((void**)&bufA, g_bufA);
    cudaGetSymbolAddress((void**)&bufB, g_bufB);
    cudaGetSymbolAddress((void**)&wt,   g_wt);

    float* out = (float*)d_out;
    float* idxOutF = (out_size >= RR * INC + RR) ? (out + (size_t)RR * INC) : nullptr;

    // prep: transform all weights + codebook transpose + norms
    k_wtransform<<<256, 256>>>(enc_w1, wt + WT_OFF_E1, INC, HC);
    k_wtransform<<<512, 256>>>(enc_w2, wt + WT_OFF_E2, HC, DC);
    k_wtransform<<<512, 256>>>(dec_w1, wt + WT_OFF_D1, DC, HC);
    k_wtransform<<<256, 256>>>(dec_w2, wt + WT_OFF_D2, HC, INC);
    k_cbT<<<512, 256>>>(cb);
    k_cnorm<<<KC, 256>>>(cb);

    dim3 g512(4, RR / 128);   // (4, 256)
    dim3 g80(1, RR / 128);

    // encoder
    k_convgemm<INC, HC, true,  false><<<g512, 256>>>(mels, wt + WT_OFF_E1, enc_b1, bufA);
    k_convgemm<HC,  DC, false, false><<<g512, 256>>>(bufA, wt + WT_OFF_E2, enc_b2, bufB);

    // VQ (z in bufB) -> g_idx
    k_vq<<<RR / 128, 256>>>(bufB, idxOutF);

    // decoder (conv1 gathers codebook rows via g_idx directly)
    k_convgemm<DC, HC, true,  true ><<<g512, 256>>>(cb,   wt + WT_OFF_D1, dec_b1, bufA);
    k_convgemm<HC, INC, false, false><<<g80, 256>>>(bufA, wt + WT_OFF_D2, dec_b2, out);
}

// round 6
// speedup vs baseline: 1.5663x; 1.3216x over previous
#include <cuda_runtime.h>
#include <cuda_bf16.h>
#include <math_constants.h>
#include <cstdint>

// ---------------- problem constants ----------------
#define BB   16
#define TT   2048
#define INC  80
#define HC   512
#define DC   512
#define KC   1024
#define RR   (BB*TT)          // 32768 rows

// ---------------- scratch ----------------
__device__ float g_bufA[(size_t)RR * DC];
__device__ float g_bufB[(size_t)RR * DC];
__device__ float g_wt[3*INC*HC + 3*HC*DC];            // fp32 enc weights
__device__ __align__(16) __nv_bfloat16 g_whi[983040]; // dec weights hi
__device__ __align__(16) __nv_bfloat16 g_wlo[983040]; // dec weights lo
__device__ float g_cbT[DC * KC];
__device__ float g_cnorm[KC];
__device__ int   g_idx[RR];

#define WT_OFF_E1 0                         // [240, 512]
#define WT_OFF_E2 (WT_OFF_E1 + 3*INC*HC)    // [1536, 512]
// bf16 regions, layout [KPAD][COUTP]
#define WO_D1 0               // [1536][512]
#define WO_D2 786432          // [1536][128]

// ---------------- mma/ldmatrix helpers (baseline PTX, sm_80+) -------------
__device__ __forceinline__ uint32_t smem_u32(const void* p) {
    uint32_t a;
    asm("{ .reg .u64 t; cvta.to.shared.u64 t, %1; cvt.u32.u64 %0, t; }"
        : "=r"(a) : "l"(p));
    return a;
}
__device__ __forceinline__ void ldsm_x4(uint32_t* r, uint32_t addr) {
    asm volatile("ldmatrix.sync.aligned.m8n8.x4.shared.b16 {%0,%1,%2,%3}, [%4];"
                 : "=r"(r[0]), "=r"(r[1]), "=r"(r[2]), "=r"(r[3]) : "r"(addr));
}
__device__ __forceinline__ void ldsm_x4t(uint32_t* r, uint32_t addr) {
    asm volatile("ldmatrix.sync.aligned.m8n8.x4.trans.shared.b16 {%0,%1,%2,%3}, [%4];"
                 : "=r"(r[0]), "=r"(r[1]), "=r"(r[2]), "=r"(r[3]) : "r"(addr));
}
__device__ __forceinline__ void mma16816(float* c, const uint32_t* a,
                                         const uint32_t* b) {
    asm volatile(
        "mma.sync.aligned.m16n8k16.row.col.f32.bf16.bf16.f32 "
        "{%0,%1,%2,%3}, {%4,%5,%6,%7}, {%8,%9}, {%0,%1,%2,%3};"
        : "+f"(c[0]), "+f"(c[1]), "+f"(c[2]), "+f"(c[3])
        : "r"(a[0]), "r"(a[1]), "r"(a[2]), "r"(a[3]), "r"(b[0]), "r"(b[1]));
}
#define STS128(a, r0, r1, r2, r3) \
    asm volatile("st.shared.v4.b32 [%0], {%1,%2,%3,%4};" \
                 :: "r"(a), "r"(r0), "r"(r1), "r"(r2), "r"(r3) : "memory")

__device__ __forceinline__ uint32_t pack2bf(float a, float b) {
    __nv_bfloat162 h = __floats2bfloat162_rn(a, b);
    return *reinterpret_cast<uint32_t*>(&h);
}

// ---------------- prep kernels --------------------------------------------
// fp32: w[Cout,Cin,3] -> wt[3*Cin, Cout]
__global__ void k_wtransform(const float* __restrict__ w, float* __restrict__ wt,
                             int Cin, int Cout) {
    int n = 3 * Cin * Cout;
    for (int i = blockIdx.x * blockDim.x + threadIdx.x; i < n;
         i += gridDim.x * blockDim.x) {
        int k  = i / Cout;
        int co = i - k * Cout;
        int dt = k / Cin;
        int ci = k - dt * Cin;
        wt[i] = w[(co * Cin + ci) * 3 + dt];
    }
}
// bf16 split: w[Cout,Cin,3] -> hi/lo [3*CinP][CoutP]
__global__ void k_wprep(const float* __restrict__ w, __nv_bfloat16* __restrict__ hi,
                        __nv_bfloat16* __restrict__ lo,
                        int Cin, int Cout, int CinP, int CoutP) {
    int kpad = 3 * CinP;
    int n = kpad * CoutP;
    for (int i = blockIdx.x * blockDim.x + threadIdx.x; i < n;
         i += gridDim.x * blockDim.x) {
        int kp = i / CoutP;
        int nn = i - kp * CoutP;
        int dt = kp / CinP;
        int ci = kp - dt * CinP;
        float v = (nn < Cout && ci < Cin) ? w[(nn * Cin + ci) * 3 + dt] : 0.f;
        __nv_bfloat16 h = __float2bfloat16_rn(v);
        hi[i] = h;
        lo[i] = __float2bfloat16_rn(v - __bfloat162float(h));
    }
}
__global__ void k_cbT(const float* __restrict__ cb) {
    int n = DC * KC;
    for (int i = blockIdx.x * blockDim.x + threadIdx.x; i < n;
         i += gridDim.x * blockDim.x) {
        int d = i >> 10;
        int k = i & (KC - 1);
        g_cbT[i] = cb[k * DC + d];
    }
}
__global__ void k_cnorm(const float* __restrict__ cb) {
    int k = blockIdx.x;
    float s = 0.f;
    for (int d = threadIdx.x; d < DC; d += 256) {
        float v = cb[k * DC + d];
        s += v * v;
    }
    __shared__ float red[256];
    red[threadIdx.x] = s;
    __syncthreads();
    for (int o = 128; o > 0; o >>= 1) {
        if (threadIdx.x < o) red[threadIdx.x] += red[threadIdx.x + o];
        __syncthreads();
    }
    if (threadIdx.x == 0) g_cnorm[k] = red[0];
}

// ---------------- fp32 conv GEMM (encoder; double-buffered, validated) ----
template<int CIN, int COUT, bool RELU>
__global__ __launch_bounds__(256)
void k_convgemm(const float* __restrict__ A, const float* __restrict__ W,
                const float* __restrict__ bias, float* __restrict__ C) {
    constexpr int BM = 128, BN = 128, BK = 16, KEFF = 3 * CIN;
    __shared__ float As[2][BK][BM];
    __shared__ float Bs[2][BK][BN];

    const int tid = threadIdx.x;
    const int tx = tid & 15, ty = tid >> 4;
    const int rowBase = blockIdx.y * BM;
    const int colBase = blockIdx.x * BN;

    const int ar0 = tid >> 2, ak0 = (tid & 3) << 2;
    const int ar1 = ar0 + 64;
    const int r0 = rowBase + ar0, r1 = rowBase + ar1;
    const int t0 = r0 & (TT - 1), t1 = r1 & (TT - 1);
    const bool f0 = (t0 == 0), l0 = (t0 == TT - 1);
    const bool f1 = (t1 == 0), l1 = (t1 == TT - 1);

    const int br0 = tid >> 5;
    const int bc0 = (tid & 31) << 2;
    const int co0 = colBase + bc0;

    float4 ra0, ra1, rb0, rb1;

    auto fetch = [&](int k0) {
        const int dt = k0 / CIN;
        const int ci = k0 - dt * CIN + ak0;
        const bool z0 = (dt == 0 && f0) || (dt == 2 && l0);
        const bool z1 = (dt == 0 && f1) || (dt == 2 && l1);
        const float* p0 = A + (size_t)(r0 + dt - 1) * CIN + ci;
        const float* p1 = A + (size_t)(r1 + dt - 1) * CIN + ci;
        ra0 = z0 ? make_float4(0.f, 0.f, 0.f, 0.f) : *(const float4*)p0;
        ra1 = z1 ? make_float4(0.f, 0.f, 0.f, 0.f) : *(const float4*)p1;
        rb0 = *(const float4*)(W + (size_t)(k0 + br0) * COUT + co0);
        rb1 = *(const float4*)(W + (size_t)(k0 + br0 + 8) * COUT + co0);
    };
    auto stage = [&](int buf) {
        As[buf][ak0 + 0][ar0] = ra0.x; As[buf][ak0 + 1][ar0] = ra0.y;
        As[buf][ak0 + 2][ar0] = ra0.z; As[buf][ak0 + 3][ar0] = ra0.w;
        As[buf][ak0 + 0][ar1] = ra1.x; As[buf][ak0 + 1][ar1] = ra1.y;
        As[buf][ak0 + 2][ar1] = ra1.z; As[buf][ak0 + 3][ar1] = ra1.w;
        *(float4*)&Bs[buf][br0][bc0]     = rb0;
        *(float4*)&Bs[buf][br0 + 8][bc0] = rb1;
    };

    float acc[8][8] = {};
    auto compute = [&](int buf) {
#pragma unroll
        for (int k = 0; k < BK; k++) {
            float a[8], b[8];
            *(float4*)(a)     = *(const float4*)&As[buf][k][ty * 8];
            *(float4*)(a + 4) = *(const float4*)&As[buf][k][ty * 8 + 4];
            *(float4*)(b)     = *(const float4*)&Bs[buf][k][tx * 8];
            *(float4*)(b + 4) = *(const float4*)&Bs[buf][k][tx * 8 + 4];
#pragma unroll
            for (int i = 0; i < 8; i++)
#pragma unroll
                for (int j = 0; j < 8; j++)
                    acc[i][j] = fmaf(a[i], b[j], acc[i][j]);
        }
    };

    fetch(0);
    stage(0);
    __syncthreads();
    int buf = 0;
    for (int k0 = BK; k0 < KEFF; k0 += BK) {
        fetch(k0);
        compute(buf);
        stage(buf ^ 1);
        __syncthreads();
        buf ^= 1;
    }
    compute(buf);

#pragma unroll
    for (int i = 0; i < 8; i++) {
        const int r = rowBase + ty * 8 + i;
#pragma unroll
        for (int j4 = 0; j4 < 8; j4 += 4) {
            const int co = colBase + tx * 8 + j4;
            float4 v;
            v.x = acc[i][j4 + 0] + bias[co + 0];
            v.y = acc[i][j4 + 1] + bias[co + 1];
            v.z = acc[i][j4 + 2] + bias[co + 2];
            v.w = acc[i][j4 + 3] + bias[co + 3];
            if (RELU) {
                v.x = fmaxf(v.x, 0.f); v.y = fmaxf(v.y, 0.f);
                v.z = fmaxf(v.z, 0.f); v.w = fmaxf(v.w, 0.f);
            }
            *(float4*)(C + (size_t)r * COUT + co) = v;
        }
    }
}

// ---------------- decoder conv GEMM via mma.sync bf16 hi/lo split ----------
template<int CIN, int CINP, int COUTP, int COUT, bool RELU, bool GATHER>
__global__ __launch_bounds__(256, 1)
void k_conv_mma(const float* __restrict__ A, const __nv_bfloat16* __restrict__ Whi,
                const __nv_bfloat16* __restrict__ Wlo, const float* __restrict__ bias,
                float* __restrict__ C) {
    constexpr int KPAD = 3 * CINP;
    constexpr int NCHUNK = KPAD / 32;
    constexpr int APITCH = 40;
    constexpr int BPITCH = 136;
    constexpr int ASZ = 128 * APITCH * 2;
    constexpr int BSZ = 32 * BPITCH * 2;

    extern __shared__ __align__(16) char smem[];
    const uint32_t sb = smem_u32(smem);
    const uint32_t oAH = sb, oAL = sb + 2 * ASZ;
    const uint32_t oBH = sb + 4 * ASZ, oBL = sb + 4 * ASZ + 2 * BSZ;

    const int tid = threadIdx.x;
    const int wid = tid >> 5, lane = tid & 31;
    const int mwarp = wid >> 2, nwarp = wid & 3;
    const int rowBase = blockIdx.y * 128;
    const int colBase = blockIdx.x * 128;

    const int ar = tid >> 1, half = tid & 1;
    const int r = rowBase + ar;
    const int tloc = r & (TT - 1);
    int gi[3];
    if (GATHER) {
#pragma unroll
        for (int dt = 0; dt < 3; dt++) {
            int rr = r + dt - 1;
            rr = rr < 0 ? 0 : (rr >= RR ? RR - 1 : rr);
            gi[dt] = g_idx[rr];
        }
    }
    const int bk = tid >> 3, seg = tid & 7;

    float4 va[4];
    uint4  wh[2], wl[2];

    auto fetch = [&](int c) {
        const int dt = (c * 32) / CINP;
        const int ci0 = c * 32 - dt * CINP;
        const bool ztap = (dt == 0 && tloc == 0) || (dt == 2 && tloc == TT - 1);
        const float* src;
        if (GATHER) {
            src = A + (size_t)gi[dt] * CIN;
        } else {
            src = A + (size_t)(r + dt - 1) * CIN;
        }
#pragma unroll
        for (int j = 0; j < 4; j++) {
            const int ci = ci0 + half * 16 + j * 4;
            const bool ok = !ztap && (CIN == CINP || ci < CIN);
            va[j] = ok ? *(const float4*)(src + ci) : make_float4(0.f, 0.f, 0.f, 0.f);
        }
        const size_t g = (size_t)(c * 32 + bk) * COUTP + colBase + seg * 16;
        wh[0] = *(const uint4*)(Whi + g);
        wh[1] = *(const uint4*)(Whi + g + 8);
        wl[0] = *(const uint4*)(Wlo + g);
        wl[1] = *(const uint4*)(Wlo + g + 8);
    };

    auto stage = [&](int buf) {
        float e[16];
        *(float4*)(e)      = va[0]; *(float4*)(e + 4)  = va[1];
        *(float4*)(e + 8)  = va[2]; *(float4*)(e + 12) = va[3];
        uint32_t hp[8], lp[8];
#pragma unroll
        for (int q = 0; q < 8; q++) {
            float h0 = __bfloat162float(__float2bfloat16_rn(e[2 * q]));
            float h1 = __bfloat162float(__float2bfloat16_rn(e[2 * q + 1]));
            hp[q] = pack2bf(h0, h1);
            lp[q] = pack2bf(e[2 * q] - h0, e[2 * q + 1] - h1);
        }
        const uint32_t aoff = (uint32_t)(ar * APITCH + half * 16) * 2 + buf * ASZ;
        STS128(oAH + aoff,      hp[0], hp[1], hp[2], hp[3]);
        STS128(oAH + aoff + 16, hp[4], hp[5], hp[6], hp[7]);
        STS128(oAL + aoff,      lp[0], lp[1], lp[2], lp[3]);
        STS128(oAL + aoff + 16, lp[4], lp[5], lp[6], lp[7]);
        const uint32_t boff = (uint32_t)(bk * BPITCH + seg * 16) * 2 + buf * BSZ;
        STS128(oBH + boff,      wh[0].x, wh[0].y, wh[0].z, wh[0].w);
        STS128(oBH + boff + 16, wh[1].x, wh[1].y, wh[1].z, wh[1].w);
        STS128(oBL + boff,      wl[0].x, wl[0].y, wl[0].z, wl[0].w);
        STS128(oBL + boff + 16, wl[1].x, wl[1].y, wl[1].z, wl[1].w);
    };

    float acc[4][4][4] = {};

    const uint32_t a_row = (lane & 15);
    const uint32_t a_k8  = (lane >> 4) * 8;
    const uint32_t b_k   = (lane & 15);
    const uint32_t b_n8  = (lane >> 4) * 8;

    auto compute = [&](int buf) {
        const uint32_t aH = oAH + buf * ASZ, aL = oAL + buf * ASZ;
        const uint32_t bH = oBH + buf * BSZ, bL = oBL + buf * BSZ;
#pragma unroll
        for (int ks = 0; ks < 2; ks++) {
            uint32_t AH[4][4], AL[4][4], BH[2][4], BL[2][4];
#pragma unroll
            for (int mt = 0; mt < 4; mt++) {
                const uint32_t ao =
                    ((mwarp * 64 + mt * 16 + a_row) * APITCH + ks * 16 + a_k8) * 2;
                ldsm_x4(AH[mt], aH + ao);
                ldsm_x4(AL[mt], aL + ao);
            }
#pragma unroll
            for (int pr = 0; pr < 2; pr++) {
                const uint32_t bo =
                    ((b_k + ks * 16) * BPITCH + nwarp * 32 + pr * 16 + b_n8) * 2;
                ldsm_x4t(BH[pr], bH + bo);
                ldsm_x4t(BL[pr], bL + bo);
            }
#pragma unroll
            for (int mt = 0; mt < 4; mt++)
#pragma unroll
                for (int nt = 0; nt < 4; nt++) {
                    const int pr = nt >> 1, hf = nt & 1;
                    mma16816(acc[mt][nt], AH[mt], &BH[pr][hf * 2]);
                    mma16816(acc[mt][nt], AL[mt], &BH[pr][hf * 2]);
                    mma16816(acc[mt][nt], AH[mt], &BL[pr][hf * 2]);
                }
        }
    };

    fetch(0);
    stage(0);
    __syncthreads();
    int buf = 0;
    for (int c = 1; c < NCHUNK; c++) {
        fetch(c);
        compute(buf);
        stage(buf ^ 1);
        __syncthreads();
        buf ^= 1;
    }
    compute(buf);

#pragma unroll
    for (int mt = 0; mt < 4; mt++) {
#pragma unroll
        for (int nt = 0; nt < 4; nt++) {
            const int col = colBase + nwarp * 32 + nt * 8 + (lane & 3) * 2;
            if ((COUT % 128) != 0 && col >= COUT) continue;
            const float b0 = bias[col], b1 = bias[col + 1];
            const int r0 = rowBase + mwarp * 64 + mt * 16 + (lane >> 2);
#pragma unroll
            for (int hh = 0; hh < 2; hh++) {
                float2 o;
                o.x = acc[mt][nt][hh * 2 + 0] + b0;
                o.y = acc[mt][nt][hh * 2 + 1] + b1;
                if (RELU) { o.x = fmaxf(o.x, 0.f); o.y = fmaxf(o.y, 0.f); }
                *(float2*)(C + (size_t)(r0 + hh * 8) * COUT + col) = o;
            }
        }
    }
}

// ---------------- VQ: fused scores GEMM + argmin (exact fp32) -------------
__global__ __launch_bounds__(256)
void k_vq(const float* __restrict__ Z, float* __restrict__ idxOutF) {
    constexpr int BM = 128, BN = 128, BK = 16;
    constexpr int KTILES = DC / BK;
    constexpr int NITER = (KC / BN) * KTILES;
    __shared__ float As[2][BK][BM];
    __shared__ float Bs[2][BK][BN];
    __shared__ float sval[128][17];
    __shared__ int   sidx[128][17];

    const int tid = threadIdx.x;
    const int tx = tid & 15, ty = tid >> 4;
    const int rowBase = blockIdx.x * BM;
    const int ar0 = tid >> 2, ak0 = (tid & 3) << 2;
    const int ar1 = ar0 + 64;
    const int br0 = tid >> 5;
    const int bc0 = (tid & 31) << 2;
    const float* arow0 = Z + (size_t)(rowBase + ar0) * DC + ak0;
    const float* arow1 = Z + (size_t)(rowBase + ar1) * DC + ak0;

    float4 ra0, ra1, rb0, rb1;

    auto fetch = [&](int iter) {
        const int nb = (iter >> 5) << 7;
        const int d0 = (iter & 31) << 4;
        ra0 = *(const float4*)(arow0 + d0);
        ra1 = *(const float4*)(arow1 + d0);
        rb0 = *(const float4*)(g_cbT + (size_t)(d0 + br0) * KC + nb + bc0);
        rb1 = *(const float4*)(g_cbT + (size_t)(d0 + br0 + 8) * KC + nb + bc0);
    };
    auto stage = [&](int buf) {
        As[buf][ak0 + 0][ar0] = ra0.x; As[buf][ak0 + 1][ar0] = ra0.y;
        As[buf][ak0 + 2][ar0] = ra0.z; As[buf][ak0 + 3][ar0] = ra0.w;
        As[buf][ak0 + 0][ar1] = ra1.x; As[buf][ak0 + 1][ar1] = ra1.y;
        As[buf][ak0 + 2][ar1] = ra1.z; As[buf][ak0 + 3][ar1] = ra1.w;
        *(float4*)&Bs[buf][br0][bc0]     = rb0;
        *(float4*)&Bs[buf][br0 + 8][bc0] = rb1;
    };

    float acc[8][8];
    float minv[8];
    int   mini[8];
#pragma unroll
    for (int i = 0; i < 8; i++) { minv[i] = CUDART_INF_F; mini[i] = 0; }

    auto compute = [&](int buf) {
#pragma unroll
        for (int k = 0; k < BK; k++) {
            float a[8], bmat[8];
            *(float4*)(a)        = *(const float4*)&As[buf][k][ty * 8];
            *(float4*)(a + 4)    = *(const float4*)&As[buf][k][ty * 8 + 4];
            *(float4*)(bmat)     = *(const float4*)&Bs[buf][k][tx * 8];
            *(float4*)(bmat + 4) = *(const float4*)&Bs[buf][k][tx * 8 + 4];
#pragma unroll
            for (int i = 0; i < 8; i++)
#pragma unroll
                for (int j = 0; j < 8; j++)
                    acc[i][j] = fmaf(a[i], bmat[j], acc[i][j]);
        }
    };

    fetch(0);
    stage(0);
    __syncthreads();
    int buf = 0;
    for (int iter = 0; iter < NITER; iter++) {
        if ((iter & (KTILES - 1)) == 0) {
#pragma unroll
            for (int i = 0; i < 8; i++)
#pragma unroll
                for (int j = 0; j < 8; j++) acc[i][j] = 0.f;
        }
        const bool more = (iter + 1 < NITER);
        if (more) fetch(iter + 1);
        compute(buf);
        if ((iter & (KTILES - 1)) == KTILES - 1) {
            const int nb = (iter >> 5) << 7;
#pragma unroll
            for (int j = 0; j < 8; j++) {
                const int kk = nb + tx * 8 + j;
                const float cn = g_cnorm[kk];
#pragma unroll
                for (int i = 0; i < 8; i++) {
                    float s = fmaf(-2.f, acc[i][j], cn);
                    if (s < minv[i]) { minv[i] = s; mini[i] = kk; }
                }
            }
        }
        if (more) {
            stage(buf ^ 1);
            __syncthreads();
            buf ^= 1;
        }
    }

#pragma unroll
    for (int i = 0; i < 8; i++) {
        sval[ty * 8 + i][tx] = minv[i];
        sidx[ty * 8 + i][tx] = mini[i];
    }
    __syncthreads();
    if (tid < 128) {
        float bv = sval[tid][0];
        int   bi = sidx[tid][0];
#pragma unroll
        for (int x = 1; x < 16; x++) {
            float v = sval[tid][x];
            int   ii = sidx[tid][x];
            if (v < bv || (v == bv && ii < bi)) { bv = v; bi = ii; }
        }
        g_idx[rowBase + tid] = bi;
        if (idxOutF) idxOutF[rowBase + tid] = (float)bi;
    }
}

// ---------------- launch ---------------------------------------------------
extern "C" void kernel_launch(void* const* d_in, const int* in_sizes, int n_in,
                              void* d_out, int out_size) {
    const float* mels   = (const float*)d_in[0];
    const float* enc_w1 = (const float*)d_in[1];
    const float* enc_b1 = (const float*)d_in[2];
    const float* enc_w2 = (const float*)d_in[3];
    const float* enc_b2 = (const float*)d_in[4];
    const float* cb     = (const float*)d_in[5];
    const float* dec_w1 = (const float*)d_in[6];
    const float* dec_b1 = (const float*)d_in[7];
    const float* dec_w2 = (const float*)d_in[8];
    const float* dec_b2 = (const float*)d_in[9];

    float *bufA, *bufB, *wt;
    __nv_bfloat16 *whi, *wlo;
    cudaGetSymbolAddress((void**)&bufA, g_bufA);
    cudaGetSymbolAddress((void**)&bufB, g_bufB);
    cudaGetSymbolAddress((void**)&wt,   g_wt);
    cudaGetSymbolAddress((void**)&whi,  g_whi);
    cudaGetSymbolAddress((void**)&wlo,  g_wlo);

    float* out = (float*)d_out;
    float* idxOutF = (out_size >= RR * INC + RR) ? (out + (size_t)RR * INC) : nullptr;

    // prep
    k_wtransform<<<256, 256>>>(enc_w1, wt + WT_OFF_E1, INC, HC);
    k_wtransform<<<512, 256>>>(enc_w2, wt + WT_OFF_E2, HC, DC);
    k_wprep<<<512, 256>>>(dec_w1, whi + WO_D1, wlo + WO_D1, DC, HC, 512, 512);
    k_wprep<<<256, 256>>>(dec_w2, whi + WO_D2, wlo + WO_D2, HC, INC, 512, 128);
    k_cbT<<<512, 256>>>(cb);
    k_cnorm<<<KC, 256>>>(cb);

    constexpr int SMEM = 4 * (128 * 40 * 2) + 4 * (32 * 136 * 2);  // 75776 B
    cudaFuncSetAttribute((const void*)k_conv_mma<DC, 512, 512, HC, true, true>,
                         cudaFuncAttributeMaxDynamicSharedMemorySize, SMEM);
    cudaFuncSetAttribute((const void*)k_conv_mma<HC, 512, 128, INC, false, false>,
                         cudaFuncAttributeMaxDynamicSharedMemorySize, SMEM);

    dim3 g512(4, RR / 128);

    // encoder (exact fp32 — protects argmin)
    k_convgemm<INC, HC, true ><<<g512, 256>>>(mels, wt + WT_OFF_E1, enc_b1, bufA);
    k_convgemm<HC,  DC, false><<<g512, 256>>>(bufA, wt + WT_OFF_E2, enc_b2, bufB);

    // VQ (exact fp32) -> g_idx
    k_vq<<<RR / 128, 256>>>(bufB, idxOutF);

    // decoder via bf16-split tensor cores (smooth error only)
    k_conv_mma<DC, 512, 512, HC, true, true>
        <<<dim3(4, RR / 128), 256, SMEM>>>(cb, whi + WO_D1, wlo + WO_D1, dec_b1, bufA);
    k_conv_mma<HC, 512, 128, INC, false, false>
        <<<dim3(1, RR / 128), 256, SMEM>>>(bufA, whi + WO_D2, wlo + WO_D2, dec_b2, out);
}